// round 12
// baseline (speedup 1.0000x reference)
#include <cuda_runtime.h>
#include <cuda_fp16.h>
#include <cstdint>
#include <cstddef>

#define B_  2
#define S_  2048
#define H_  2048
#define NH_ 16
#define NKV_ 8
#define HD_ 128
#define BS_ 4096
#define SCALE_ 0.08838834764831845f
#define QKVN 6144

// ---------------- scratch ----------------
__device__ float  g_qkvraw[(size_t)BS_ * QKVN];               // q|gate (4096) | k (1024) | v (1024)
__device__ __half g_hidh [(size_t)BS_ * H_];
__device__ __half g_wqkvh[(size_t)QKVN * H_];
__device__ __half g_woh  [(size_t)H_ * 2048];
__device__ __half g_qh   [(size_t)B_ * NH_  * S_ * HD_];
__device__ __half g_kh   [(size_t)B_ * NKV_ * S_ * HD_];
__device__ __half g_vth  [(size_t)B_ * NKV_ * HD_ * S_];
__device__ __half g_avh  [(size_t)BS_ * 2048];
__device__ __half g_ph   [(size_t)B_ * NH_ * S_ * S_];

__device__ __forceinline__ uint32_t smem_u32(const void* p) {
    uint32_t a;
    asm("{ .reg .u64 t; cvta.to.shared.u64 t, %1; cvt.u32.u64 %0, t; }" : "=r"(a) : "l"(p));
    return a;
}
__device__ __forceinline__ void cp16(uint32_t dst, const void* src) {
    asm volatile("cp.async.ca.shared.global [%0], [%1], 16;" :: "r"(dst), "l"(src));
}
#define CP_COMMIT() asm volatile("cp.async.commit_group;" ::: "memory")
#define CP_WAIT0()  asm volatile("cp.async.wait_group 0;" ::: "memory")

// fp16 fragment permutation within a 32-k group:
// k = 16h + 8j + 2t + e  ->  pos = 8t + 4h + 2j + e
__device__ __forceinline__ int permh(int k) {
    int t = (k >> 1) & 3, e = k & 1, j = (k >> 3) & 1, h = (k >> 4) & 1;
    return (t << 3) + (h << 2) + (j << 1) + e;
}

// ---------------- input transform ----------------
__global__ void round_perm_h(const float* __restrict__ in, __half* __restrict__ out, long long n)
{
    long long i = (long long)blockIdx.x * 256 + threadIdx.x;
    if (i >= n) return;
    long long o = (i & ~31LL) | (long long)permh((int)(i & 31));
    out[o] = __float2half(in[i]);
}

// ---------------- fp16 mma GEMM (R6 core): C = alpha * A(MxK) * B(NxK)^T ----------------
// CTA 128x128, K-tile 32 halves (64B rows), 256 threads, 8 warps (each 64x32).
// Smem per matrix per buffer: 128 rows x 64B = 8KB, chunk-swizzled (c ^= row&3). 2 CTA/SM.
// MODE 0: C (fp32) = alpha*acc. MODE 2: PV epilogue -> Ch (fp16, gated, permuted av layout).
template<int MODE>
__global__ __launch_bounds__(256, 2) void gemm_h(
    const __half* __restrict__ A, const __half* __restrict__ Bm,
    float* __restrict__ C, __half* __restrict__ Ch, const float* __restrict__ gateraw,
    int M, int N, int K,
    long long sA, long long sB, long long sC,
    float alpha, int gqaB)
{
    __shared__ __align__(128) char sm[32768];   // [A0|A1|B0|B1] x 8KB
    const uint32_t sbase = smem_u32(sm);

    const int z = blockIdx.z;
    int bb = 0, hh = 0;
    long long offB;
    if (gqaB) { bb = z >> 4; hh = z & 15; offB = ((long long)bb * NKV_ + (hh >> 1)) * sB; }
    else        offB = (long long)z * sB;
    A  += (long long)z * sA;
    Bm += offB;

    const int tid  = threadIdx.x;
    const int lane = tid & 31;
    const int wid  = tid >> 5;
    const int g    = lane >> 2;
    const int tig  = lane & 3;
    const int warpM = (wid >> 2) * 64;
    const int warpN = (wid & 3) * 32;

    // staging: row = tid>>1 (0..127), chunks cc0, cc0+1
    const int crow = tid >> 1;
    const int cc0  = (tid & 1) << 1;
    const char* Asrc = (const char*)(A  + (long long)(blockIdx.y * 128 + crow) * K) + cc0 * 16;
    const char* Bsrc = (const char*)(Bm + (long long)(blockIdx.x * 128 + crow) * K) + cc0 * 16;
    const uint32_t dA0 = sbase + (uint32_t)(crow * 64 + ((cc0     ^ (crow & 3)) << 4));
    const uint32_t dA1 = sbase + (uint32_t)(crow * 64 + (((cc0+1) ^ (crow & 3)) << 4));
    const uint32_t boff = 16384u;

    const uint32_t tc = (uint32_t)((tig ^ (g & 3)) << 4);   // fragment chunk byte offset

    float acc[4][4][4] = {};
    const int nK = K >> 5;

    // prologue: tile 0 -> buffer 0
    cp16(dA0, Asrc);          cp16(dA1, Asrc + 16);
    cp16(dA0 + boff, Bsrc);   cp16(dA1 + boff, Bsrc + 16);
    CP_COMMIT(); CP_WAIT0();
    __syncthreads();

    int buf = 0;
    for (int kt = 0; kt < nK; kt++) {
        const bool has_next = (kt + 1 < nK);
        const int nb = buf ^ 1;
        if (has_next) {
            const int kb = (kt + 1) << 6;  // bytes per row step
            cp16(dA0 + nb * 8192, Asrc + kb);          cp16(dA1 + nb * 8192, Asrc + kb + 16);
            cp16(dA0 + boff + nb * 8192, Bsrc + kb);   cp16(dA1 + boff + nb * 8192, Bsrc + kb + 16);
            CP_COMMIT();
        }

        const char* Ab = sm + buf * 8192;
        const char* Bb = sm + 16384 + buf * 8192;
        uint4 fa0[4], fa1[4], fb[4];
        #pragma unroll
        for (int i = 0; i < 4; i++) {
            const int r = warpM + i * 16 + g;
            fa0[i] = *(const uint4*)(Ab + r * 64 + tc);
            fa1[i] = *(const uint4*)(Ab + (r + 8) * 64 + tc);
        }
        #pragma unroll
        for (int j = 0; j < 4; j++) {
            const int rn = warpN + j * 8 + g;
            fb[j] = *(const uint4*)(Bb + rn * 64 + tc);
        }
        #pragma unroll
        for (int i = 0; i < 4; i++)
            #pragma unroll
            for (int j = 0; j < 4; j++) {
                asm volatile(
                    "mma.sync.aligned.m16n8k16.row.col.f32.f16.f16.f32 "
                    "{%0,%1,%2,%3}, {%4,%5,%6,%7}, {%8,%9}, {%0,%1,%2,%3};"
                    : "+f"(acc[i][j][0]), "+f"(acc[i][j][1]),
                      "+f"(acc[i][j][2]), "+f"(acc[i][j][3])
                    : "r"(fa0[i].x), "r"(fa1[i].x), "r"(fa0[i].y), "r"(fa1[i].y),
                      "r"(fb[j].x), "r"(fb[j].y));
            }
        #pragma unroll
        for (int i = 0; i < 4; i++)
            #pragma unroll
            for (int j = 0; j < 4; j++) {
                asm volatile(
                    "mma.sync.aligned.m16n8k16.row.col.f32.f16.f16.f32 "
                    "{%0,%1,%2,%3}, {%4,%5,%6,%7}, {%8,%9}, {%0,%1,%2,%3};"
                    : "+f"(acc[i][j][0]), "+f"(acc[i][j][1]),
                      "+f"(acc[i][j][2]), "+f"(acc[i][j][3])
                    : "r"(fa0[i].z), "r"(fa1[i].z), "r"(fa0[i].w), "r"(fa1[i].w),
                      "r"(fb[j].z), "r"(fb[j].w));
            }

        if (has_next) CP_WAIT0();
        __syncthreads();
        buf = nb;
    }

    // ---- epilogue ----
    if (MODE == 0) {
        float* Cz = C + (long long)z * sC;
        #pragma unroll
        for (int i = 0; i < 4; i++) {
            const int r0 = blockIdx.y * 128 + warpM + i * 16 + g;
            #pragma unroll
            for (int j = 0; j < 4; j++) {
                const int c0 = blockIdx.x * 128 + warpN + j * 8 + 2 * tig;
                float2 v0 = { acc[i][j][0] * alpha, acc[i][j][1] * alpha };
                float2 v1 = { acc[i][j][2] * alpha, acc[i][j][3] * alpha };
                *(float2*)(&Cz[(long long)r0 * N + c0])       = v0;
                *(float2*)(&Cz[(long long)(r0 + 8) * N + c0]) = v1;
            }
        }
    } else {
        // PV: avh[(bs<<11) + hh*128 + perm(d)] = half(acc * sigmoid(gate))
        #pragma unroll
        for (int i = 0; i < 4; i++) {
            const int r0 = blockIdx.y * 128 + warpM + i * 16 + g;
            const long long bs0 = (long long)bb * S_ + r0;
            const long long bs1 = bs0 + 8;
            #pragma unroll
            for (int j = 0; j < 4; j++) {
                #pragma unroll
                for (int u = 0; u < 2; u++) {
                    const int d  = warpN + j * 8 + 2 * tig + u;
                    const int pd = (d & ~31) | permh(d & 31);
                    float g0 = gateraw[bs0 * QKVN + hh * 256 + 128 + d];
                    float g1 = gateraw[bs1 * QKVN + hh * 256 + 128 + d];
                    Ch[(bs0 << 11) + hh * 128 + pd] = __float2half(acc[i][j][u]     / (1.f + __expf(-g0)));
                    Ch[(bs1 << 11) + hh * 128 + pd] = __float2half(acc[i][j][2 + u] / (1.f + __expf(-g1)));
                }
            }
        }
    }
}

// ---------------- RMSNorm + RoPE (emit fp16, fragment-permuted) ----------------
__global__ void qnorm_rope(const float* __restrict__ qkvraw, const float* __restrict__ cosb,
                           const float* __restrict__ sinb, const float* __restrict__ w,
                           __half* __restrict__ q)
{
    int s = blockIdx.x, h = blockIdx.y, b = blockIdx.z;
    int d = threadIdx.x;
    long long bs = (long long)b * S_ + s;
    float x = qkvraw[bs * QKVN + h * 256 + d];
    float t = x * x;
    #pragma unroll
    for (int o = 16; o; o >>= 1) t += __shfl_xor_sync(0xffffffffu, t, o);
    __shared__ float ws[4];
    if ((d & 31) == 0) ws[d >> 5] = t;
    __syncthreads();
    float var = (ws[0] + ws[1] + ws[2] + ws[3]) * (1.0f / 128.0f);
    float xn = x * rsqrtf(var + 1e-6f) * w[d];
    __shared__ float sh[128];
    sh[d] = xn;
    __syncthreads();
    float other = (d < 64) ? -sh[d + 64] : sh[d - 64];
    float c = cosb[bs * 128 + d], sn = sinb[bs * 128 + d];
    int pd = (d & ~31) | permh(d & 31);
    q[(((long long)b * NH_ + h) * S_ + s) * HD_ + pd] = __float2half(xn * c + other * sn);
}

__global__ void knorm_rope(const float* __restrict__ qkvraw, const float* __restrict__ cosb,
                           const float* __restrict__ sinb, const float* __restrict__ w,
                           __half* __restrict__ k)
{
    int s = blockIdx.x, h = blockIdx.y, b = blockIdx.z;
    int d = threadIdx.x;
    long long bs = (long long)b * S_ + s;
    float x = qkvraw[bs * QKVN + 4096 + h * 128 + d];
    float t = x * x;
    #pragma unroll
    for (int o = 16; o; o >>= 1) t += __shfl_xor_sync(0xffffffffu, t, o);
    __shared__ float ws[4];
    if ((d & 31) == 0) ws[d >> 5] = t;
    __syncthreads();
    float var = (ws[0] + ws[1] + ws[2] + ws[3]) * (1.0f / 128.0f);
    float xn = x * rsqrtf(var + 1e-6f) * w[d];
    __shared__ float sh[128];
    sh[d] = xn;
    __syncthreads();
    float other = (d < 64) ? -sh[d + 64] : sh[d - 64];
    float c = cosb[bs * 128 + d], sn = sinb[bs * 128 + d];
    int pd = (d & ~31) | permh(d & 31);
    k[(((long long)b * NKV_ + h) * S_ + s) * HD_ + pd] = __float2half(xn * c + other * sn);
}

// ---------------- V transpose -> fp16 [z][d][perm(s)] ----------------
__global__ void vtrans_kernel(const float* __restrict__ qkvraw, __half* __restrict__ vt)
{
    __shared__ float tile[32][33];
    int z = blockIdx.z; int b = z >> 3; int kvh = z & 7;
    int s0 = blockIdx.x * 32;
    int d0 = blockIdx.y * 32;
    int tx = threadIdx.x;
    int ty = threadIdx.y;
    for (int r = ty; r < 32; r += 8)
        tile[r][tx] = qkvraw[((size_t)(b * S_ + s0 + r)) * QKVN + 5120 + kvh * 128 + d0 + tx];
    __syncthreads();
    int ptx = permh(tx);
    for (int r = ty; r < 32; r += 8)
        vt[((size_t)z * 128 + d0 + r) * 2048 + s0 + ptx] = __float2half(tile[tx][r]);
}

// ---------------- softmax (vectorized) + fp16 permuted copy ----------------
__global__ __launch_bounds__(256) void softmax_kernel(float* __restrict__ attn, __half* __restrict__ ph)
{
    int qi = blockIdx.x;
    int z  = blockIdx.y;
    float* row = attn + ((size_t)z * S_ + qi) * S_;
    __half* hrow = ph + ((size_t)z * S_ + qi) * S_;
    int tid = threadIdx.x;
    __shared__ float p[2048];
    float4* p4 = (float4*)p;
    float4* row4 = (float4*)row;

    float mn = 3.4e38f, mx = -3.4e38f;
    #pragma unroll
    for (int it = 0; it < 2; it++) {
        int c4 = tid + it * 256;
        float4 v = row4[c4];
        p4[c4] = v;
        mn = fminf(mn, fminf(fminf(v.x, v.y), fminf(v.z, v.w)));
        int c = c4 << 2;
        if (c     <= qi) mx = fmaxf(mx, v.x);
        if (c + 1 <= qi) mx = fmaxf(mx, v.y);
        if (c + 2 <= qi) mx = fmaxf(mx, v.z);
        if (c + 3 <= qi) mx = fmaxf(mx, v.w);
    }
    #pragma unroll
    for (int o = 16; o; o >>= 1) {
        mn = fminf(mn, __shfl_xor_sync(0xffffffffu, mn, o));
        mx = fmaxf(mx, __shfl_xor_sync(0xffffffffu, mx, o));
    }
    __shared__ float smn[8], smx[8], ssum[8];
    if ((tid & 31) == 0) { smn[tid >> 5] = mn; smx[tid >> 5] = mx; }
    __syncthreads();
    mn = smn[0]; mx = smx[0];
    #pragma unroll
    for (int i = 1; i < 8; i++) { mn = fminf(mn, smn[i]); mx = fmaxf(mx, smx[i]); }
    float mval = mn - 20.f;
    float M = fmaxf(mx, mval);

    float sum = 0.f;
    #pragma unroll
    for (int it = 0; it < 2; it++) {
        int c4 = tid + it * 256;
        int c = c4 << 2;
        float4 v = p4[c4];
        float4 e;
        e.x = __expf(((c     <= qi) ? v.x : mval) - M);
        e.y = __expf(((c + 1 <= qi) ? v.y : mval) - M);
        e.z = __expf(((c + 2 <= qi) ? v.z : mval) - M);
        e.w = __expf(((c + 3 <= qi) ? v.w : mval) - M);
        p4[c4] = e;
        sum += (e.x + e.y) + (e.z + e.w);
    }
    #pragma unroll
    for (int o = 16; o; o >>= 1) sum += __shfl_xor_sync(0xffffffffu, sum, o);
    if ((tid & 31) == 0) ssum[tid >> 5] = sum;
    __syncthreads();
    sum = ssum[0];
    #pragma unroll
    for (int i = 1; i < 8; i++) sum += ssum[i];
    float inv = 1.f / sum;

    __half2* hrow2 = (__half2*)hrow;
    #pragma unroll
    for (int it = 0; it < 2; it++) {
        int c4 = tid + it * 256;
        int c = c4 << 2;
        float4 e = p4[c4];
        float4 pr = { e.x * inv, e.y * inv, e.z * inv, e.w * inv };
        row4[c4] = pr;
        // permh keeps even/odd pairs adjacent: permh(2t)=8t, so write half2 pairs
        int pd0 = (c & ~31) | permh(c & 31);
        int pd2 = ((c + 2) & ~31) | permh((c + 2) & 31);
        hrow2[pd0 >> 1] = __floats2half2_rn(pr.x, pr.y);
        hrow2[pd2 >> 1] = __floats2half2_rn(pr.z, pr.w);
    }
}

// ---------------- launch ----------------
extern "C" void kernel_launch(void* const* d_in, const int* in_sizes, int n_in,
                              void* d_out, int out_size)
{
    const float* hidden = (const float*)d_in[0];
    const float* cosb   = (const float*)d_in[1];
    const float* sinb   = (const float*)d_in[2];
    const float* Wq = (const float*)d_in[4];
    const float* Wk = (const float*)d_in[5];
    const float* Wv = (const float*)d_in[6];
    const float* Wo = (const float*)d_in[7];
    const float* qw = (const float*)d_in[8];
    const float* kw = (const float*)d_in[9];

    float* out  = (float*)d_out;
    float* attn = out + (size_t)B_ * S_ * H_;

    float* qkvraw;
    __half *hidh, *wqkvh, *woh, *qh, *kh, *vth, *avh, *ph;
    cudaGetSymbolAddress((void**)&qkvraw, g_qkvraw);
    cudaGetSymbolAddress((void**)&hidh,  g_hidh);
    cudaGetSymbolAddress((void**)&wqkvh, g_wqkvh);
    cudaGetSymbolAddress((void**)&woh,   g_woh);
    cudaGetSymbolAddress((void**)&qh,    g_qh);
    cudaGetSymbolAddress((void**)&kh,    g_kh);
    cudaGetSymbolAddress((void**)&vth,   g_vth);
    cudaGetSymbolAddress((void**)&avh,   g_avh);
    cudaGetSymbolAddress((void**)&ph,    g_ph);

    // 0) convert + permute operands; Wq|Wk|Wv concatenated into [6144,2048] fp16
    {
        long long nh = (long long)BS_ * H_;
        round_perm_h<<<(unsigned)((nh + 255) / 256), 256>>>(hidden, hidh, nh);
        long long nq = 4096LL * H_;
        round_perm_h<<<(unsigned)((nq + 255) / 256), 256>>>(Wq, wqkvh, nq);
        long long nk = 1024LL * H_;
        round_perm_h<<<(unsigned)((nk + 255) / 256), 256>>>(Wk, wqkvh + (size_t)4096 * H_, nk);
        round_perm_h<<<(unsigned)((nk + 255) / 256), 256>>>(Wv, wqkvh + (size_t)5120 * H_, nk);
        long long no = 2048LL * 2048LL;
        round_perm_h<<<(unsigned)((no + 255) / 256), 256>>>(Wo, woh, no);
    }

    // 1) fused QKV projection: [4096 x 6144]
    gemm_h<0><<<dim3(48, 32, 1), 256>>>(hidh, wqkvh, qkvraw, nullptr, nullptr,
                                        4096, QKVN, 2048, 0, 0, 0, 1.f, 0);

    // 2) norms + rope + layout
    qnorm_rope<<<dim3(S_, NH_, B_), 128>>>(qkvraw, cosb, sinb, qw, qh);
    knorm_rope<<<dim3(S_, NKV_, B_), 128>>>(qkvraw, cosb, sinb, kw, kh);
    vtrans_kernel<<<dim3(64, 4, 16), dim3(32, 8)>>>(qkvraw, vth);

    // 3) scores = scale * Q K^T
    gemm_h<0><<<dim3(16, 16, 32), 256>>>(qh, kh, attn, nullptr, nullptr, 2048, 2048, 128,
                                         (long long)S_ * HD_, (long long)S_ * HD_,
                                         (long long)S_ * S_, SCALE_, 1);

    // 4) softmax + fp16 permuted copy
    softmax_kernel<<<dim3(S_, B_ * NH_), 256>>>(attn, ph);

    // 5) P @ V, fused sigmoid gate -> avh
    gemm_h<2><<<dim3(1, 16, 32), 256>>>(ph, vth, nullptr, avh, qkvraw, 2048, 128, 2048,
                                        (long long)S_ * S_, (long long)HD_ * S_, 0, 1.f, 1);

    // 6) output projection
    gemm_h<0><<<dim3(16, 32, 1), 256>>>(avh, woh, out, nullptr, nullptr, 4096, 2048, 2048, 0, 0, 0, 1.f, 0);
}

// round 13
// speedup vs baseline: 1.0260x; 1.0260x over previous
#include <cuda_runtime.h>
#include <cuda_fp16.h>
#include <cstdint>
#include <cstddef>

#define B_  2
#define S_  2048
#define H_  2048
#define NH_ 16
#define NKV_ 8
#define HD_ 128
#define BS_ 4096
#define SCALE_ 0.08838834764831845f
#define QKVN 6144

// ---------------- scratch ----------------
__device__ float  g_qkvraw[(size_t)BS_ * QKVN];               // q|gate (4096) | k (1024) | v (1024)
__device__ __half g_hidh [(size_t)BS_ * H_];
__device__ __half g_wqkvh[(size_t)QKVN * H_];
__device__ __half g_woh  [(size_t)H_ * 2048];
__device__ __half g_qh   [(size_t)B_ * NH_  * S_ * HD_];
__device__ __half g_kh   [(size_t)B_ * NKV_ * S_ * HD_];
__device__ __half g_vth  [(size_t)B_ * NKV_ * HD_ * S_];
__device__ __half g_avh  [(size_t)BS_ * 2048];
__device__ __half g_ph   [(size_t)B_ * NH_ * S_ * S_];

__device__ __forceinline__ uint32_t smem_u32(const void* p) {
    uint32_t a;
    asm("{ .reg .u64 t; cvta.to.shared.u64 t, %1; cvt.u32.u64 %0, t; }" : "=r"(a) : "l"(p));
    return a;
}
__device__ __forceinline__ void cp16(uint32_t dst, const void* src) {
    asm volatile("cp.async.ca.shared.global [%0], [%1], 16;" :: "r"(dst), "l"(src));
}
#define CP_COMMIT() asm volatile("cp.async.commit_group;" ::: "memory")
#define CP_WAIT1()  asm volatile("cp.async.wait_group 1;" ::: "memory")

// fp16 fragment permutation within a 32-k group:
// k = 16h + 8j + 2t + e  ->  pos = 8t + 4h + 2j + e
__device__ __forceinline__ int permh(int k) {
    int t = (k >> 1) & 3, e = k & 1, j = (k >> 3) & 1, h = (k >> 4) & 1;
    return (t << 3) + (h << 2) + (j << 1) + e;
}

// ---------------- input transform ----------------
__global__ void round_perm_h(const float* __restrict__ in, __half* __restrict__ out, long long n)
{
    long long i = (long long)blockIdx.x * 256 + threadIdx.x;
    if (i >= n) return;
    long long o = (i & ~31LL) | (long long)permh((int)(i & 31));
    out[o] = __float2half(in[i]);
}

// ---------------- fp16 mma GEMM (R6 core, 3-stage): C = alpha * A(MxK) * B(NxK)^T ----------------
// CTA 128x128, K-tile 32 halves (64B rows), 256 threads, 8 warps (each 64x32).
// Smem: 3 stages x (A 8KB + B 8KB) = 48KB dynamic, chunk-swizzled (c ^= row&3). 2 CTA/SM.
// MODE 0: C (fp32) = alpha*acc. MODE 2: PV epilogue -> Ch (fp16, gated, permuted av layout).
#define GH_SMEM 49152
template<int MODE>
__global__ __launch_bounds__(256, 2) void gemm_h(
    const __half* __restrict__ A, const __half* __restrict__ Bm,
    float* __restrict__ C, __half* __restrict__ Ch, const float* __restrict__ gateraw,
    int M, int N, int K,
    long long sA, long long sB, long long sC,
    float alpha, int gqaB)
{
    extern __shared__ __align__(128) char sm[];
    const uint32_t sbase = smem_u32(sm);

    const int z = blockIdx.z;
    int bb = 0, hh = 0;
    long long offB;
    if (gqaB) { bb = z >> 4; hh = z & 15; offB = ((long long)bb * NKV_ + (hh >> 1)) * sB; }
    else        offB = (long long)z * sB;
    A  += (long long)z * sA;
    Bm += offB;

    const int tid  = threadIdx.x;
    const int lane = tid & 31;
    const int wid  = tid >> 5;
    const int g    = lane >> 2;
    const int tig  = lane & 3;
    const int warpM = (wid >> 2) * 64;
    const int warpN = (wid & 3) * 32;

    // staging: row = tid>>1 (0..127), chunks cc0, cc0+1
    const int crow = tid >> 1;
    const int cc0  = (tid & 1) << 1;
    const char* Asrc = (const char*)(A  + (long long)(blockIdx.y * 128 + crow) * K) + cc0 * 16;
    const char* Bsrc = (const char*)(Bm + (long long)(blockIdx.x * 128 + crow) * K) + cc0 * 16;
    const uint32_t aO0 = (uint32_t)(crow * 64 + ((cc0       ^ (crow & 3)) << 4));
    const uint32_t aO1 = (uint32_t)(crow * 64 + (((cc0 + 1) ^ (crow & 3)) << 4));
    const uint32_t bBase = 24576u;

    const uint32_t tc = (uint32_t)((tig ^ (g & 3)) << 4);   // fragment chunk byte offset

    float acc[4][4][4] = {};
    const int nK = K >> 5;

    // prologue: stages 0 and 1
    #pragma unroll
    for (int s = 0; s < 2; s++) {
        if (s < nK) {
            const int kb = s << 6;
            const uint32_t st = (uint32_t)s * 8192u;
            cp16(sbase + st + aO0, Asrc + kb);
            cp16(sbase + st + aO1, Asrc + kb + 16);
            cp16(sbase + bBase + st + aO0, Bsrc + kb);
            cp16(sbase + bBase + st + aO1, Bsrc + kb + 16);
        }
        CP_COMMIT();
    }

    int s0 = 0, s2 = 2;
    for (int kt = 0; kt < nK; kt++) {
        CP_WAIT1();
        __syncthreads();

        const char* Ab = sm + s0 * 8192;
        const char* Bb = sm + 24576 + s0 * 8192;
        uint4 fa0[4], fa1[4], fb[4];
        #pragma unroll
        for (int i = 0; i < 4; i++) {
            const int r = warpM + i * 16 + g;
            fa0[i] = *(const uint4*)(Ab + r * 64 + tc);
            fa1[i] = *(const uint4*)(Ab + (r + 8) * 64 + tc);
        }
        #pragma unroll
        for (int j = 0; j < 4; j++) {
            const int rn = warpN + j * 8 + g;
            fb[j] = *(const uint4*)(Bb + rn * 64 + tc);
        }

        if (kt + 2 < nK) {
            const int kb = (kt + 2) << 6;
            const uint32_t st = (uint32_t)s2 * 8192u;
            cp16(sbase + st + aO0, Asrc + kb);
            cp16(sbase + st + aO1, Asrc + kb + 16);
            cp16(sbase + bBase + st + aO0, Bsrc + kb);
            cp16(sbase + bBase + st + aO1, Bsrc + kb + 16);
        }
        CP_COMMIT();

        #pragma unroll
        for (int i = 0; i < 4; i++)
            #pragma unroll
            for (int j = 0; j < 4; j++) {
                asm volatile(
                    "mma.sync.aligned.m16n8k16.row.col.f32.f16.f16.f32 "
                    "{%0,%1,%2,%3}, {%4,%5,%6,%7}, {%8,%9}, {%0,%1,%2,%3};"
                    : "+f"(acc[i][j][0]), "+f"(acc[i][j][1]),
                      "+f"(acc[i][j][2]), "+f"(acc[i][j][3])
                    : "r"(fa0[i].x), "r"(fa1[i].x), "r"(fa0[i].y), "r"(fa1[i].y),
                      "r"(fb[j].x), "r"(fb[j].y));
            }
        #pragma unroll
        for (int i = 0; i < 4; i++)
            #pragma unroll
            for (int j = 0; j < 4; j++) {
                asm volatile(
                    "mma.sync.aligned.m16n8k16.row.col.f32.f16.f16.f32 "
                    "{%0,%1,%2,%3}, {%4,%5,%6,%7}, {%8,%9}, {%0,%1,%2,%3};"
                    : "+f"(acc[i][j][0]), "+f"(acc[i][j][1]),
                      "+f"(acc[i][j][2]), "+f"(acc[i][j][3])
                    : "r"(fa0[i].z), "r"(fa1[i].z), "r"(fa0[i].w), "r"(fa1[i].w),
                      "r"(fb[j].z), "r"(fb[j].w));
            }

        s0 = (s0 == 2) ? 0 : s0 + 1;
        s2 = (s2 == 2) ? 0 : s2 + 1;
    }

    // ---- epilogue ----
    if (MODE == 0) {
        float* Cz = C + (long long)z * sC;
        #pragma unroll
        for (int i = 0; i < 4; i++) {
            const int r0 = blockIdx.y * 128 + warpM + i * 16 + g;
            #pragma unroll
            for (int j = 0; j < 4; j++) {
                const int c0 = blockIdx.x * 128 + warpN + j * 8 + 2 * tig;
                float2 v0 = { acc[i][j][0] * alpha, acc[i][j][1] * alpha };
                float2 v1 = { acc[i][j][2] * alpha, acc[i][j][3] * alpha };
                *(float2*)(&Cz[(long long)r0 * N + c0])       = v0;
                *(float2*)(&Cz[(long long)(r0 + 8) * N + c0]) = v1;
            }
        }
    } else {
        // PV: avh[(bs<<11) + hh*128 + perm(d)] = half(acc * sigmoid(gate))
        #pragma unroll
        for (int i = 0; i < 4; i++) {
            const int r0 = blockIdx.y * 128 + warpM + i * 16 + g;
            const long long bs0 = (long long)bb * S_ + r0;
            const long long bs1 = bs0 + 8;
            #pragma unroll
            for (int j = 0; j < 4; j++) {
                #pragma unroll
                for (int u = 0; u < 2; u++) {
                    const int d  = warpN + j * 8 + 2 * tig + u;
                    const int pd = (d & ~31) | permh(d & 31);
                    float g0 = gateraw[bs0 * QKVN + hh * 256 + 128 + d];
                    float g1 = gateraw[bs1 * QKVN + hh * 256 + 128 + d];
                    Ch[(bs0 << 11) + hh * 128 + pd] = __float2half(acc[i][j][u]     / (1.f + __expf(-g0)));
                    Ch[(bs1 << 11) + hh * 128 + pd] = __float2half(acc[i][j][2 + u] / (1.f + __expf(-g1)));
                }
            }
        }
    }
}

// ---------------- RMSNorm + RoPE (emit fp16, fragment-permuted) ----------------
__global__ void qnorm_rope(const float* __restrict__ qkvraw, const float* __restrict__ cosb,
                           const float* __restrict__ sinb, const float* __restrict__ w,
                           __half* __restrict__ q)
{
    int s = blockIdx.x, h = blockIdx.y, b = blockIdx.z;
    int d = threadIdx.x;
    long long bs = (long long)b * S_ + s;
    float x = qkvraw[bs * QKVN + h * 256 + d];
    float t = x * x;
    #pragma unroll
    for (int o = 16; o; o >>= 1) t += __shfl_xor_sync(0xffffffffu, t, o);
    __shared__ float ws[4];
    if ((d & 31) == 0) ws[d >> 5] = t;
    __syncthreads();
    float var = (ws[0] + ws[1] + ws[2] + ws[3]) * (1.0f / 128.0f);
    float xn = x * rsqrtf(var + 1e-6f) * w[d];
    __shared__ float sh[128];
    sh[d] = xn;
    __syncthreads();
    float other = (d < 64) ? -sh[d + 64] : sh[d - 64];
    float c = cosb[bs * 128 + d], sn = sinb[bs * 128 + d];
    int pd = (d & ~31) | permh(d & 31);
    q[(((long long)b * NH_ + h) * S_ + s) * HD_ + pd] = __float2half(xn * c + other * sn);
}

__global__ void knorm_rope(const float* __restrict__ qkvraw, const float* __restrict__ cosb,
                           const float* __restrict__ sinb, const float* __restrict__ w,
                           __half* __restrict__ k)
{
    int s = blockIdx.x, h = blockIdx.y, b = blockIdx.z;
    int d = threadIdx.x;
    long long bs = (long long)b * S_ + s;
    float x = qkvraw[bs * QKVN + 4096 + h * 128 + d];
    float t = x * x;
    #pragma unroll
    for (int o = 16; o; o >>= 1) t += __shfl_xor_sync(0xffffffffu, t, o);
    __shared__ float ws[4];
    if ((d & 31) == 0) ws[d >> 5] = t;
    __syncthreads();
    float var = (ws[0] + ws[1] + ws[2] + ws[3]) * (1.0f / 128.0f);
    float xn = x * rsqrtf(var + 1e-6f) * w[d];
    __shared__ float sh[128];
    sh[d] = xn;
    __syncthreads();
    float other = (d < 64) ? -sh[d + 64] : sh[d - 64];
    float c = cosb[bs * 128 + d], sn = sinb[bs * 128 + d];
    int pd = (d & ~31) | permh(d & 31);
    k[(((long long)b * NKV_ + h) * S_ + s) * HD_ + pd] = __float2half(xn * c + other * sn);
}

// ---------------- V transpose -> fp16 [z][d][perm(s)] ----------------
__global__ void vtrans_kernel(const float* __restrict__ qkvraw, __half* __restrict__ vt)
{
    __shared__ float tile[32][33];
    int z = blockIdx.z; int b = z >> 3; int kvh = z & 7;
    int s0 = blockIdx.x * 32;
    int d0 = blockIdx.y * 32;
    int tx = threadIdx.x;
    int ty = threadIdx.y;
    for (int r = ty; r < 32; r += 8)
        tile[r][tx] = qkvraw[((size_t)(b * S_ + s0 + r)) * QKVN + 5120 + kvh * 128 + d0 + tx];
    __syncthreads();
    int ptx = permh(tx);
    for (int r = ty; r < 32; r += 8)
        vt[((size_t)z * 128 + d0 + r) * 2048 + s0 + ptx] = __float2half(tile[tx][r]);
}

// ---------------- softmax (vectorized) + fp16 permuted copy ----------------
__global__ __launch_bounds__(256) void softmax_kernel(float* __restrict__ attn, __half* __restrict__ ph)
{
    int qi = blockIdx.x;
    int z  = blockIdx.y;
    float* row = attn + ((size_t)z * S_ + qi) * S_;
    __half* hrow = ph + ((size_t)z * S_ + qi) * S_;
    int tid = threadIdx.x;
    __shared__ float p[2048];
    float4* p4 = (float4*)p;
    float4* row4 = (float4*)row;

    float mn = 3.4e38f, mx = -3.4e38f;
    #pragma unroll
    for (int it = 0; it < 2; it++) {
        int c4 = tid + it * 256;
        float4 v = row4[c4];
        p4[c4] = v;
        mn = fminf(mn, fminf(fminf(v.x, v.y), fminf(v.z, v.w)));
        int c = c4 << 2;
        if (c     <= qi) mx = fmaxf(mx, v.x);
        if (c + 1 <= qi) mx = fmaxf(mx, v.y);
        if (c + 2 <= qi) mx = fmaxf(mx, v.z);
        if (c + 3 <= qi) mx = fmaxf(mx, v.w);
    }
    #pragma unroll
    for (int o = 16; o; o >>= 1) {
        mn = fminf(mn, __shfl_xor_sync(0xffffffffu, mn, o));
        mx = fmaxf(mx, __shfl_xor_sync(0xffffffffu, mx, o));
    }
    __shared__ float smn[8], smx[8], ssum[8];
    if ((tid & 31) == 0) { smn[tid >> 5] = mn; smx[tid >> 5] = mx; }
    __syncthreads();
    mn = smn[0]; mx = smx[0];
    #pragma unroll
    for (int i = 1; i < 8; i++) { mn = fminf(mn, smn[i]); mx = fmaxf(mx, smx[i]); }
    float mval = mn - 20.f;
    float M = fmaxf(mx, mval);

    float sum = 0.f;
    #pragma unroll
    for (int it = 0; it < 2; it++) {
        int c4 = tid + it * 256;
        int c = c4 << 2;
        float4 v = p4[c4];
        float4 e;
        e.x = __expf(((c     <= qi) ? v.x : mval) - M);
        e.y = __expf(((c + 1 <= qi) ? v.y : mval) - M);
        e.z = __expf(((c + 2 <= qi) ? v.z : mval) - M);
        e.w = __expf(((c + 3 <= qi) ? v.w : mval) - M);
        p4[c4] = e;
        sum += (e.x + e.y) + (e.z + e.w);
    }
    #pragma unroll
    for (int o = 16; o; o >>= 1) sum += __shfl_xor_sync(0xffffffffu, sum, o);
    if ((tid & 31) == 0) ssum[tid >> 5] = sum;
    __syncthreads();
    sum = ssum[0];
    #pragma unroll
    for (int i = 1; i < 8; i++) sum += ssum[i];
    float inv = 1.f / sum;

    __half2* hrow2 = (__half2*)hrow;
    #pragma unroll
    for (int it = 0; it < 2; it++) {
        int c4 = tid + it * 256;
        int c = c4 << 2;
        float4 e = p4[c4];
        float4 pr = { e.x * inv, e.y * inv, e.z * inv, e.w * inv };
        row4[c4] = pr;
        int pd0 = (c & ~31) | permh(c & 31);
        int pd2 = ((c + 2) & ~31) | permh((c + 2) & 31);
        hrow2[pd0 >> 1] = __floats2half2_rn(pr.x, pr.y);
        hrow2[pd2 >> 1] = __floats2half2_rn(pr.z, pr.w);
    }
}

// ---------------- launch ----------------
extern "C" void kernel_launch(void* const* d_in, const int* in_sizes, int n_in,
                              void* d_out, int out_size)
{
    const float* hidden = (const float*)d_in[0];
    const float* cosb   = (const float*)d_in[1];
    const float* sinb   = (const float*)d_in[2];
    const float* Wq = (const float*)d_in[4];
    const float* Wk = (const float*)d_in[5];
    const float* Wv = (const float*)d_in[6];
    const float* Wo = (const float*)d_in[7];
    const float* qw = (const float*)d_in[8];
    const float* kw = (const float*)d_in[9];

    float* out  = (float*)d_out;
    float* attn = out + (size_t)B_ * S_ * H_;

    float* qkvraw;
    __half *hidh, *wqkvh, *woh, *qh, *kh, *vth, *avh, *ph;
    cudaGetSymbolAddress((void**)&qkvraw, g_qkvraw);
    cudaGetSymbolAddress((void**)&hidh,  g_hidh);
    cudaGetSymbolAddress((void**)&wqkvh, g_wqkvh);
    cudaGetSymbolAddress((void**)&woh,   g_woh);
    cudaGetSymbolAddress((void**)&qh,    g_qh);
    cudaGetSymbolAddress((void**)&kh,    g_kh);
    cudaGetSymbolAddress((void**)&vth,   g_vth);
    cudaGetSymbolAddress((void**)&avh,   g_avh);
    cudaGetSymbolAddress((void**)&ph,    g_ph);

    cudaFuncSetAttribute(gemm_h<0>, cudaFuncAttributeMaxDynamicSharedMemorySize, GH_SMEM);
    cudaFuncSetAttribute(gemm_h<2>, cudaFuncAttributeMaxDynamicSharedMemorySize, GH_SMEM);

    // 0) convert + permute operands; Wq|Wk|Wv concatenated into [6144,2048] fp16
    {
        long long nh = (long long)BS_ * H_;
        round_perm_h<<<(unsigned)((nh + 255) / 256), 256>>>(hidden, hidh, nh);
        long long nq = 4096LL * H_;
        round_perm_h<<<(unsigned)((nq + 255) / 256), 256>>>(Wq, wqkvh, nq);
        long long nk = 1024LL * H_;
        round_perm_h<<<(unsigned)((nk + 255) / 256), 256>>>(Wk, wqkvh + (size_t)4096 * H_, nk);
        round_perm_h<<<(unsigned)((nk + 255) / 256), 256>>>(Wv, wqkvh + (size_t)5120 * H_, nk);
        long long no = 2048LL * 2048LL;
        round_perm_h<<<(unsigned)((no + 255) / 256), 256>>>(Wo, woh, no);
    }

    // 1) fused QKV projection: [4096 x 6144]
    gemm_h<0><<<dim3(48, 32, 1), 256, GH_SMEM>>>(hidh, wqkvh, qkvraw, nullptr, nullptr,
                                        4096, QKVN, 2048, 0, 0, 0, 1.f, 0);

    // 2) norms + rope + layout
    qnorm_rope<<<dim3(S_, NH_, B_), 128>>>(qkvraw, cosb, sinb, qw, qh);
    knorm_rope<<<dim3(S_, NKV_, B_), 128>>>(qkvraw, cosb, sinb, kw, kh);
    vtrans_kernel<<<dim3(64, 4, 16), dim3(32, 8)>>>(qkvraw, vth);

    // 3) scores = scale * Q K^T
    gemm_h<0><<<dim3(16, 16, 32), 256, GH_SMEM>>>(qh, kh, attn, nullptr, nullptr, 2048, 2048, 128,
                                         (long long)S_ * HD_, (long long)S_ * HD_,
                                         (long long)S_ * S_, SCALE_, 1);

    // 4) softmax + fp16 permuted copy
    softmax_kernel<<<dim3(S_, B_ * NH_), 256>>>(attn, ph);

    // 5) P @ V, fused sigmoid gate -> avh
    gemm_h<2><<<dim3(1, 16, 32), 256, GH_SMEM>>>(ph, vth, nullptr, avh, qkvraw, 2048, 128, 2048,
                                        (long long)S_ * S_, (long long)HD_ * S_, 0, 1.f, 1);

    // 6) output projection
    gemm_h<0><<<dim3(16, 32, 1), 256, GH_SMEM>>>(avh, woh, out, nullptr, nullptr, 4096, 2048, 2048, 0, 0, 0, 1.f, 0);
}

// round 15
// speedup vs baseline: 1.0266x; 1.0006x over previous
#include <cuda_runtime.h>
#include <cuda_fp16.h>
#include <cstdint>
#include <cstddef>

#define B_  2
#define S_  2048
#define H_  2048
#define NH_ 16
#define NKV_ 8
#define HD_ 128
#define BS_ 4096
#define SCALE_ 0.08838834764831845f
#define QKVN 6144

// ---------------- scratch ----------------
__device__ float  g_qkvraw[(size_t)BS_ * QKVN];               // q|gate (4096) | k (1024) | v (1024)
__device__ __half g_hidh [(size_t)BS_ * H_];
__device__ __half g_wqkvh[(size_t)QKVN * H_];
__device__ __half g_woh  [(size_t)H_ * 2048];
__device__ __half g_qh   [(size_t)B_ * NH_  * S_ * HD_];
__device__ __half g_kh   [(size_t)B_ * NKV_ * S_ * HD_];
__device__ __half g_vth  [(size_t)B_ * NKV_ * HD_ * S_];
__device__ __half g_avh  [(size_t)BS_ * 2048];
__device__ __half g_ph   [(size_t)B_ * NH_ * S_ * S_];

__device__ __forceinline__ uint32_t smem_u32(const void* p) {
    uint32_t a;
    asm("{ .reg .u64 t; cvta.to.shared.u64 t, %1; cvt.u32.u64 %0, t; }" : "=r"(a) : "l"(p));
    return a;
}
__device__ __forceinline__ void cp16(uint32_t dst, const void* src) {
    asm volatile("cp.async.ca.shared.global [%0], [%1], 16;" :: "r"(dst), "l"(src));
}
#define CP_COMMIT() asm volatile("cp.async.commit_group;" ::: "memory")
#define CP_WAIT1()  asm volatile("cp.async.wait_group 1;" ::: "memory")

// fp16 fragment permutation within a 32-k group:
// k = 16h + 8j + 2t + e  ->  pos = 8t + 4h + 2j + e
__device__ __forceinline__ int permh(int k) {
    int t = (k >> 1) & 3, e = k & 1, j = (k >> 3) & 1, h = (k >> 4) & 1;
    return (t << 3) + (h << 2) + (j << 1) + e;
}

// ---------------- fused input transform: all 5 operands in one launch ----------------
// segments: hidden(8388608) | Wq(8388608) | Wk(2097152) | Wv(2097152) | Wo(4194304)
__global__ void round_perm_all(const float* __restrict__ hidden, const float* __restrict__ Wq,
                               const float* __restrict__ Wk, const float* __restrict__ Wv,
                               const float* __restrict__ Wo,
                               __half* __restrict__ hidh, __half* __restrict__ wqkvh,
                               __half* __restrict__ woh)
{
    long long i = (long long)blockIdx.x * 256 + threadIdx.x;
    const float* src;
    __half* dst;
    long long off;
    if (i < 8388608LL)            { src = hidden; dst = hidh;  off = i; }
    else if (i < 16777216LL)      { src = Wq; dst = wqkvh;              off = i - 8388608LL; }
    else if (i < 18874368LL)      { src = Wk; dst = wqkvh + 8388608LL;  off = i - 16777216LL; }
    else if (i < 20971520LL)      { src = Wv; dst = wqkvh + 10485760LL; off = i - 18874368LL; }
    else                          { src = Wo; dst = woh;                off = i - 20971520LL; }
    long long o = (off & ~31LL) | (long long)permh((int)(off & 31));
    dst[o] = __float2half(src[off]);
}

// ---------------- fp16 mma GEMM (R6 core, 3-stage): C = alpha * A(MxK) * B(NxK)^T ----------------
// CTA 128x128, K-tile 32 halves (64B rows), 256 threads, 8 warps (each 64x32).
// Smem: 3 stages x (A 8KB + B 8KB) = 48KB dynamic, chunk-swizzled (c ^= row&3). 2 CTA/SM.
// MODE 0: C (fp32) = alpha*acc. MODE 2: PV epilogue -> Ch (fp16, gated, permuted av layout).
#define GH_SMEM 49152
template<int MODE>
__global__ __launch_bounds__(256, 2) void gemm_h(
    const __half* __restrict__ A, const __half* __restrict__ Bm,
    float* __restrict__ C, __half* __restrict__ Ch, const float* __restrict__ gateraw,
    int M, int N, int K,
    long long sA, long long sB, long long sC,
    float alpha, int gqaB)
{
    extern __shared__ __align__(128) char sm[];
    const uint32_t sbase = smem_u32(sm);

    const int z = blockIdx.z;
    int bb = 0, hh = 0;
    long long offB;
    if (gqaB) { bb = z >> 4; hh = z & 15; offB = ((long long)bb * NKV_ + (hh >> 1)) * sB; }
    else        offB = (long long)z * sB;
    A  += (long long)z * sA;
    Bm += offB;

    const int tid  = threadIdx.x;
    const int lane = tid & 31;
    const int wid  = tid >> 5;
    const int g    = lane >> 2;
    const int tig  = lane & 3;
    const int warpM = (wid >> 2) * 64;
    const int warpN = (wid & 3) * 32;

    // staging: row = tid>>1 (0..127), chunks cc0, cc0+1
    const int crow = tid >> 1;
    const int cc0  = (tid & 1) << 1;
    const char* Asrc = (const char*)(A  + (long long)(blockIdx.y * 128 + crow) * K) + cc0 * 16;
    const char* Bsrc = (const char*)(Bm + (long long)(blockIdx.x * 128 + crow) * K) + cc0 * 16;
    const uint32_t aO0 = (uint32_t)(crow * 64 + ((cc0       ^ (crow & 3)) << 4));
    const uint32_t aO1 = (uint32_t)(crow * 64 + (((cc0 + 1) ^ (crow & 3)) << 4));
    const uint32_t bBase = 24576u;

    const uint32_t tc = (uint32_t)((tig ^ (g & 3)) << 4);   // fragment chunk byte offset

    float acc[4][4][4] = {};
    const int nK = K >> 5;

    // prologue: stages 0 and 1
    #pragma unroll
    for (int s = 0; s < 2; s++) {
        if (s < nK) {
            const int kb = s << 6;
            const uint32_t st = (uint32_t)s * 8192u;
            cp16(sbase + st + aO0, Asrc + kb);
            cp16(sbase + st + aO1, Asrc + kb + 16);
            cp16(sbase + bBase + st + aO0, Bsrc + kb);
            cp16(sbase + bBase + st + aO1, Bsrc + kb + 16);
        }
        CP_COMMIT();
    }

    int s0 = 0, s2 = 2;
    for (int kt = 0; kt < nK; kt++) {
        CP_WAIT1();
        __syncthreads();

        const char* Ab = sm + s0 * 8192;
        const char* Bb = sm + 24576 + s0 * 8192;
        uint4 fa0[4], fa1[4], fb[4];
        #pragma unroll
        for (int i = 0; i < 4; i++) {
            const int r = warpM + i * 16 + g;
            fa0[i] = *(const uint4*)(Ab + r * 64 + tc);
            fa1[i] = *(const uint4*)(Ab + (r + 8) * 64 + tc);
        }
        #pragma unroll
        for (int j = 0; j < 4; j++) {
            const int rn = warpN + j * 8 + g;
            fb[j] = *(const uint4*)(Bb + rn * 64 + tc);
        }

        if (kt + 2 < nK) {
            const int kb = (kt + 2) << 6;
            const uint32_t st = (uint32_t)s2 * 8192u;
            cp16(sbase + st + aO0, Asrc + kb);
            cp16(sbase + st + aO1, Asrc + kb + 16);
            cp16(sbase + bBase + st + aO0, Bsrc + kb);
            cp16(sbase + bBase + st + aO1, Bsrc + kb + 16);
        }
        CP_COMMIT();

        #pragma unroll
        for (int i = 0; i < 4; i++)
            #pragma unroll
            for (int j = 0; j < 4; j++) {
                asm volatile(
                    "mma.sync.aligned.m16n8k16.row.col.f32.f16.f16.f32 "
                    "{%0,%1,%2,%3}, {%4,%5,%6,%7}, {%8,%9}, {%0,%1,%2,%3};"
                    : "+f"(acc[i][j][0]), "+f"(acc[i][j][1]),
                      "+f"(acc[i][j][2]), "+f"(acc[i][j][3])
                    : "r"(fa0[i].x), "r"(fa1[i].x), "r"(fa0[i].y), "r"(fa1[i].y),
                      "r"(fb[j].x), "r"(fb[j].y));
            }
        #pragma unroll
        for (int i = 0; i < 4; i++)
            #pragma unroll
            for (int j = 0; j < 4; j++) {
                asm volatile(
                    "mma.sync.aligned.m16n8k16.row.col.f32.f16.f16.f32 "
                    "{%0,%1,%2,%3}, {%4,%5,%6,%7}, {%8,%9}, {%0,%1,%2,%3};"
                    : "+f"(acc[i][j][0]), "+f"(acc[i][j][1]),
                      "+f"(acc[i][j][2]), "+f"(acc[i][j][3])
                    : "r"(fa0[i].z), "r"(fa1[i].z), "r"(fa0[i].w), "r"(fa1[i].w),
                      "r"(fb[j].z), "r"(fb[j].w));
            }

        s0 = (s0 == 2) ? 0 : s0 + 1;
        s2 = (s2 == 2) ? 0 : s2 + 1;
    }

    // ---- epilogue ----
    if (MODE == 0) {
        float* Cz = C + (long long)z * sC;
        #pragma unroll
        for (int i = 0; i < 4; i++) {
            const int r0 = blockIdx.y * 128 + warpM + i * 16 + g;
            #pragma unroll
            for (int j = 0; j < 4; j++) {
                const int c0 = blockIdx.x * 128 + warpN + j * 8 + 2 * tig;
                float2 v0 = { acc[i][j][0] * alpha, acc[i][j][1] * alpha };
                float2 v1 = { acc[i][j][2] * alpha, acc[i][j][3] * alpha };
                *(float2*)(&Cz[(long long)r0 * N + c0])       = v0;
                *(float2*)(&Cz[(long long)(r0 + 8) * N + c0]) = v1;
            }
        }
    } else {
        // PV: avh[(bs<<11) + hh*128 + perm(d)] = half(acc * sigmoid(gate))
        #pragma unroll
        for (int i = 0; i < 4; i++) {
            const int r0 = blockIdx.y * 128 + warpM + i * 16 + g;
            const long long bs0 = (long long)bb * S_ + r0;
            const long long bs1 = bs0 + 8;
            #pragma unroll
            for (int j = 0; j < 4; j++) {
                #pragma unroll
                for (int u = 0; u < 2; u++) {
                    const int d  = warpN + j * 8 + 2 * tig + u;
                    const int pd = (d & ~31) | permh(d & 31);
                    float g0 = gateraw[bs0 * QKVN + hh * 256 + 128 + d];
                    float g1 = gateraw[bs1 * QKVN + hh * 256 + 128 + d];
                    Ch[(bs0 << 11) + hh * 128 + pd] = __float2half(acc[i][j][u]     / (1.f + __expf(-g0)));
                    Ch[(bs1 << 11) + hh * 128 + pd] = __float2half(acc[i][j][2 + u] / (1.f + __expf(-g1)));
                }
            }
        }
    }
}

// ---------------- RMSNorm + RoPE (emit fp16, fragment-permuted) ----------------
__global__ void qnorm_rope(const float* __restrict__ qkvraw, const float* __restrict__ cosb,
                           const float* __restrict__ sinb, const float* __restrict__ w,
                           __half* __restrict__ q)
{
    int s = blockIdx.x, h = blockIdx.y, b = blockIdx.z;
    int d = threadIdx.x;
    long long bs = (long long)b * S_ + s;
    float x = qkvraw[bs * QKVN + h * 256 + d];
    float t = x * x;
    #pragma unroll
    for (int o = 16; o; o >>= 1) t += __shfl_xor_sync(0xffffffffu, t, o);
    __shared__ float ws[4];
    if ((d & 31) == 0) ws[d >> 5] = t;
    __syncthreads();
    float var = (ws[0] + ws[1] + ws[2] + ws[3]) * (1.0f / 128.0f);
    float xn = x * rsqrtf(var + 1e-6f) * w[d];
    __shared__ float sh[128];
    sh[d] = xn;
    __syncthreads();
    float other = (d < 64) ? -sh[d + 64] : sh[d - 64];
    float c = cosb[bs * 128 + d], sn = sinb[bs * 128 + d];
    int pd = (d & ~31) | permh(d & 31);
    q[(((long long)b * NH_ + h) * S_ + s) * HD_ + pd] = __float2half(xn * c + other * sn);
}

__global__ void knorm_rope(const float* __restrict__ qkvraw, const float* __restrict__ cosb,
                           const float* __restrict__ sinb, const float* __restrict__ w,
                           __half* __restrict__ k)
{
    int s = blockIdx.x, h = blockIdx.y, b = blockIdx.z;
    int d = threadIdx.x;
    long long bs = (long long)b * S_ + s;
    float x = qkvraw[bs * QKVN + 4096 + h * 128 + d];
    float t = x * x;
    #pragma unroll
    for (int o = 16; o; o >>= 1) t += __shfl_xor_sync(0xffffffffu, t, o);
    __shared__ float ws[4];
    if ((d & 31) == 0) ws[d >> 5] = t;
    __syncthreads();
    float var = (ws[0] + ws[1] + ws[2] + ws[3]) * (1.0f / 128.0f);
    float xn = x * rsqrtf(var + 1e-6f) * w[d];
    __shared__ float sh[128];
    sh[d] = xn;
    __syncthreads();
    float other = (d < 64) ? -sh[d + 64] : sh[d - 64];
    float c = cosb[bs * 128 + d], sn = sinb[bs * 128 + d];
    int pd = (d & ~31) | permh(d & 31);
    k[(((long long)b * NKV_ + h) * S_ + s) * HD_ + pd] = __float2half(xn * c + other * sn);
}

// ---------------- V transpose -> fp16 [z][d][perm(s)] ----------------
__global__ void vtrans_kernel(const float* __restrict__ qkvraw, __half* __restrict__ vt)
{
    __shared__ float tile[32][33];
    int z = blockIdx.z; int b = z >> 3; int kvh = z & 7;
    int s0 = blockIdx.x * 32;
    int d0 = blockIdx.y * 32;
    int tx = threadIdx.x;
    int ty = threadIdx.y;
    for (int r = ty; r < 32; r += 8)
        tile[r][tx] = qkvraw[((size_t)(b * S_ + s0 + r)) * QKVN + 5120 + kvh * 128 + d0 + tx];
    __syncthreads();
    int ptx = permh(tx);
    for (int r = ty; r < 32; r += 8)
        vt[((size_t)z * 128 + d0 + r) * 2048 + s0 + ptx] = __float2half(tile[tx][r]);
}

// ---------------- softmax (vectorized) + fp16 permuted copy ----------------
__global__ __launch_bounds__(256) void softmax_kernel(float* __restrict__ attn, __half* __restrict__ ph)
{
    int qi = blockIdx.x;
    int z  = blockIdx.y;
    float* row = attn + ((size_t)z * S_ + qi) * S_;
    __half* hrow = ph + ((size_t)z * S_ + qi) * S_;
    int tid = threadIdx.x;
    __shared__ float p[2048];
    float4* p4 = (float4*)p;
    float4* row4 = (float4*)row;

    float mn = 3.4e38f, mx = -3.4e38f;
    #pragma unroll
    for (int it = 0; it < 2; it++) {
        int c4 = tid + it * 256;
        float4 v = row4[c4];
        p4[c4] = v;
        mn = fminf(mn, fminf(fminf(v.x, v.y), fminf(v.z, v.w)));
        int c = c4 << 2;
        if (c     <= qi) mx = fmaxf(mx, v.x);
        if (c + 1 <= qi) mx = fmaxf(mx, v.y);
        if (c + 2 <= qi) mx = fmaxf(mx, v.z);
        if (c + 3 <= qi) mx = fmaxf(mx, v.w);
    }
    #pragma unroll
    for (int o = 16; o; o >>= 1) {
        mn = fminf(mn, __shfl_xor_sync(0xffffffffu, mn, o));
        mx = fmaxf(mx, __shfl_xor_sync(0xffffffffu, mx, o));
    }
    __shared__ float smn[8], smx[8], ssum[8];
    if ((tid & 31) == 0) { smn[tid >> 5] = mn; smx[tid >> 5] = mx; }
    __syncthreads();
    mn = smn[0]; mx = smx[0];
    #pragma unroll
    for (int i = 1; i < 8; i++) { mn = fminf(mn, smn[i]); mx = fmaxf(mx, smx[i]); }
    float mval = mn - 20.f;
    float M = fmaxf(mx, mval);

    float sum = 0.f;
    #pragma unroll
    for (int it = 0; it < 2; it++) {
        int c4 = tid + it * 256;
        int c = c4 << 2;
        float4 v = p4[c4];
        float4 e;
        e.x = __expf(((c     <= qi) ? v.x : mval) - M);
        e.y = __expf(((c + 1 <= qi) ? v.y : mval) - M);
        e.z = __expf(((c + 2 <= qi) ? v.z : mval) - M);
        e.w = __expf(((c + 3 <= qi) ? v.w : mval) - M);
        p4[c4] = e;
        sum += (e.x + e.y) + (e.z + e.w);
    }
    #pragma unroll
    for (int o = 16; o; o >>= 1) sum += __shfl_xor_sync(0xffffffffu, sum, o);
    if ((tid & 31) == 0) ssum[tid >> 5] = sum;
    __syncthreads();
    sum = ssum[0];
    #pragma unroll
    for (int i = 1; i < 8; i++) sum += ssum[i];
    float inv = 1.f / sum;

    __half2* hrow2 = (__half2*)hrow;
    #pragma unroll
    for (int it = 0; it < 2; it++) {
        int c4 = tid + it * 256;
        int c = c4 << 2;
        float4 e = p4[c4];
        float4 pr = { e.x * inv, e.y * inv, e.z * inv, e.w * inv };
        row4[c4] = pr;
        int pd0 = (c & ~31) | permh(c & 31);
        int pd2 = ((c + 2) & ~31) | permh((c + 2) & 31);
        hrow2[pd0 >> 1] = __floats2half2_rn(pr.x, pr.y);
        hrow2[pd2 >> 1] = __floats2half2_rn(pr.z, pr.w);
    }
}

// ---------------- launch ----------------
extern "C" void kernel_launch(void* const* d_in, const int* in_sizes, int n_in,
                              void* d_out, int out_size)
{
    const float* hidden = (const float*)d_in[0];
    const float* cosb   = (const float*)d_in[1];
    const float* sinb   = (const float*)d_in[2];
    const float* Wq = (const float*)d_in[4];
    const float* Wk = (const float*)d_in[5];
    const float* Wv = (const float*)d_in[6];
    const float* Wo = (const float*)d_in[7];
    const float* qw = (const float*)d_in[8];
    const float* kw = (const float*)d_in[9];

    float* out  = (float*)d_out;
    float* attn = out + (size_t)B_ * S_ * H_;

    float* qkvraw;
    __half *hidh, *wqkvh, *woh, *qh, *kh, *vth, *avh, *ph;
    cudaGetSymbolAddress((void**)&qkvraw, g_qkvraw);
    cudaGetSymbolAddress((void**)&hidh,  g_hidh);
    cudaGetSymbolAddress((void**)&wqkvh, g_wqkvh);
    cudaGetSymbolAddress((void**)&woh,   g_woh);
    cudaGetSymbolAddress((void**)&qh,    g_qh);
    cudaGetSymbolAddress((void**)&kh,    g_kh);
    cudaGetSymbolAddress((void**)&vth,   g_vth);
    cudaGetSymbolAddress((void**)&avh,   g_avh);
    cudaGetSymbolAddress((void**)&ph,    g_ph);

    cudaFuncSetAttribute(gemm_h<0>, cudaFuncAttributeMaxDynamicSharedMemorySize, GH_SMEM);
    cudaFuncSetAttribute(gemm_h<2>, cudaFuncAttributeMaxDynamicSharedMemorySize, GH_SMEM);

    // 0) fused convert + permute of all external operands (1 launch, 25.2M elems)
    round_perm_all<<<98304, 256>>>(hidden, Wq, Wk, Wv, Wo, hidh, wqkvh, woh);

    // 1) fused QKV projection: [4096 x 6144]
    gemm_h<0><<<dim3(48, 32, 1), 256, GH_SMEM>>>(hidh, wqkvh, qkvraw, nullptr, nullptr,
                                        4096, QKVN, 2048, 0, 0, 0, 1.f, 0);

    // 2) norms + rope + layout
    qnorm_rope<<<dim3(S_, NH_, B_), 128>>>(qkvraw, cosb, sinb, qw, qh);
    knorm_rope<<<dim3(S_, NKV_, B_), 128>>>(qkvraw, cosb, sinb, kw, kh);
    vtrans_kernel<<<dim3(64, 4, 16), dim3(32, 8)>>>(qkvraw, vth);

    // 3) scores = scale * Q K^T   (launch index 5 -> ncu capture window)
    gemm_h<0><<<dim3(16, 16, 32), 256, GH_SMEM>>>(qh, kh, attn, nullptr, nullptr, 2048, 2048, 128,
                                         (long long)S_ * HD_, (long long)S_ * HD_,
                                         (long long)S_ * S_, SCALE_, 1);

    // 4) softmax + fp16 permuted copy
    softmax_kernel<<<dim3(S_, B_ * NH_), 256>>>(attn, ph);

    // 5) P @ V, fused sigmoid gate -> avh
    gemm_h<2><<<dim3(1, 16, 32), 256, GH_SMEM>>>(ph, vth, nullptr, avh, qkvraw, 2048, 128, 2048,
                                        (long long)S_ * S_, (long long)HD_ * S_, 0, 1.f, 1);

    // 6) output projection
    gemm_h<0><<<dim3(16, 32, 1), 256, GH_SMEM>>>(avh, woh, out, nullptr, nullptr, 4096, 2048, 2048, 0, 0, 0, 1.f, 0);
}